// round 8
// baseline (speedup 1.0000x reference)
#include <cuda_runtime.h>
#include <cstdint>

#define T_STEPS 200
#define HID     20
#define NTHR    256      // 8 warps: sub = warp&3 (gate quarter), kh = warp>>2 (k half)
#define EPB     64       // elements per block (2 per thread)
#define KH      10       // k per half

typedef unsigned long long ULL;

// ---------- packed f32x2 helpers (Blackwell FFMA2/FADD2; PTX-only) ----------
#define FMA2(d, a, b, c) \
    asm("fma.rn.f32x2 %0, %1, %2, %3;" : "=l"(d) : "l"(a), "l"(b), "l"(c))
#define ADD2(d, a, b) \
    asm("add.rn.f32x2 %0, %1, %2;" : "=l"(d) : "l"(a), "l"(b))

__device__ __forceinline__ ULL pack2(float x, float y) {
    ULL r;
    asm("mov.b64 %0, {%1, %2};" : "=l"(r)
        : "r"(__float_as_uint(x)), "r"(__float_as_uint(y)));
    return r;
}
__device__ __forceinline__ void unpack2(ULL v, float &x, float &y) {
    unsigned lo, hi;
    asm("mov.b64 {%0, %1}, %2;" : "=r"(lo), "=r"(hi) : "l"(v));
    x = __uint_as_float(lo);
    y = __uint_as_float(hi);
}

// ---------- fast activations (MUFU EX2+RCP, ~1e-6 rel err) ----------
__device__ __forceinline__ float sigm(float x) {
    return __fdividef(1.0f, 1.0f + __expf(-x));
}
__device__ __forceinline__ float tanh_fast(float x) {
    float ax = fabsf(x);
    float e  = __expf(-2.0f * ax);
    float r  = __fdividef(1.0f - e, 1.0f + e);
    return copysignf(r, x);
}

// ---------- exact JAX threefry2x32 (20 rounds) ----------
__device__ __forceinline__ void threefry2x32(unsigned k0, unsigned k1,
                                             unsigned x0, unsigned x1,
                                             unsigned &o0, unsigned &o1) {
    unsigned ks2 = k0 ^ k1 ^ 0x1BD11BDAu;
    x0 += k0; x1 += k1;
#define TFR(r) { x0 += x1; x1 = (x1 << r) | (x1 >> (32 - r)); x1 ^= x0; }
    TFR(13) TFR(15) TFR(26) TFR(6)
    x0 += k1;  x1 += ks2 + 1u;
    TFR(17) TFR(29) TFR(16) TFR(24)
    x0 += ks2; x1 += k0 + 2u;
    TFR(13) TFR(15) TFR(26) TFR(6)
    x0 += k0;  x1 += k1 + 3u;
    TFR(17) TFR(29) TFR(16) TFR(24)
    x0 += k1;  x1 += ks2 + 4u;
    TFR(13) TFR(15) TFR(26) TFR(6)
    x0 += ks2; x1 += k0 + 5u;
#undef TFR
    o0 = x0; o1 = x1;
}
// JAX partitionable threefry: ctr=(0,j), bits = o0^o1  (key (0,42))
__device__ __forceinline__ unsigned jax_random_bits_partitionable(unsigned j) {
    unsigned o0, o1;
    threefry2x32(0u, 42u, 0u, j, o0, o1);
    return o0 ^ o1;
}

// One k-contribution for two elements: 5 broadcast LDS.128 -> 20 FFMA2.
// h values arrive pre-duplicated as packed (h,h).
__device__ __forceinline__ void mv_accum2(ULL* gpa, ULL* gpb,
                                          ULL h2a, ULL h2b,
                                          const float4* __restrict__ wrow) {
    const ulonglong2* r = reinterpret_cast<const ulonglong2*>(wrow);
#pragma unroll
    for (int q = 0; q < 5; q++) {
        ulonglong2 w = r[q];
        FMA2(gpa[2 * q],     h2a, w.x, gpa[2 * q]);
        FMA2(gpa[2 * q + 1], h2a, w.y, gpa[2 * q + 1]);
        FMA2(gpb[2 * q],     h2b, w.x, gpb[2 * q]);
        FMA2(gpb[2 * q + 1], h2b, w.y, gpb[2 * q + 1]);
    }
}

// gp layout (units u0..u0+4): gp[2q],gp[2q+1] (q<4) = gate-group q for units
// (u0..u0+3); gp[8]=(i4,f4), gp[9]=(g4,o4) for unit u0+4
__device__ __forceinline__ void cell_update(ULL* gp, float* c, float* hout) {
    float iv[5], fv[5], gv[5], ov[5];
    unpack2(gp[0], iv[0], iv[1]); unpack2(gp[1], iv[2], iv[3]);
    unpack2(gp[2], fv[0], fv[1]); unpack2(gp[3], fv[2], fv[3]);
    unpack2(gp[4], gv[0], gv[1]); unpack2(gp[5], gv[2], gv[3]);
    unpack2(gp[6], ov[0], ov[1]); unpack2(gp[7], ov[2], ov[3]);
    unpack2(gp[8], iv[4], fv[4]);
    unpack2(gp[9], gv[4], ov[4]);
#pragma unroll
    for (int j = 0; j < 5; j++) {
        float cv = fmaf(sigm(fv[j]), c[j], sigm(iv[j]) * tanh_fast(gv[j]));
        c[j] = cv;
        hout[j] = sigm(ov[j]) * tanh_fast(cv);
    }
}

// dynamic shared layout (bytes)
#define OFF_SW    0                      // float4 [3][20][4][5]   = 19200
#define OFF_SWX   19200                  // float4 [2][4][5]       = 640
#define OFF_SBIAS 19840                  // float4 [2][4][5]       = 640
#define OFF_SH    20480                  // ULL [2][64][21]        = 21504
#define OFF_SEX   41984                  // ULL [256][11]          = 22528
#define OFF_SLG   64512                  // float [3][4][64]       = 3072
#define SMEM_TOTAL 67584

__global__ void __launch_bounds__(NTHR, 2)
lstm_fused_kernel(const float* __restrict__ x,
                  const float* __restrict__ h0,
                  const float* __restrict__ c0,
                  const float* __restrict__ Wih0,
                  const float* __restrict__ Whh0,
                  const float* __restrict__ bih0,
                  const float* __restrict__ bhh0,
                  const float* __restrict__ Wih1,
                  const float* __restrict__ Whh1,
                  const float* __restrict__ bih1,
                  const float* __restrict__ bhh1,
                  const float* __restrict__ Wdec,
                  const float* __restrict__ bdec,
                  float* __restrict__ out,
                  int B) {
    extern __shared__ __align__(16) char dsm[];
    float4* sW    = reinterpret_cast<float4*>(dsm + OFF_SW);     // [m][k][sub][q]
    float4* sWx   = reinterpret_cast<float4*>(dsm + OFF_SWX);    // [i][sub][q]
    float4* sBias = reinterpret_cast<float4*>(dsm + OFF_SBIAS);  // [l][sub][q]
    ULL*    sH    = reinterpret_cast<ULL*>(dsm + OFF_SH);        // [l][e][21], (h,h)
    ULL*    sEx   = reinterpret_cast<ULL*>(dsm + OFF_SEX);       // [tid][11]
    float*  sLG   = reinterpret_cast<float*>(dsm + OFF_SLG);     // [a][sub][e]

#define SW(m, k, s, q) sW[(((m) * HID + (k)) * 4 + (s)) * 5 + (q)]
#define SWX(i, s, q)   sWx[((i) * 4 + (s)) * 5 + (q)]
#define SBIAS(l, s, q) sBias[((l) * 4 + (s)) * 5 + (q)]
#define SH(l, e, k)    sH[((l) * EPB + (e)) * 21 + (k)]
#define SEX(t, j)      sEx[(t) * 11 + (j)]
#define SLG(a, s, e)   sLG[((a) * 4 + (s)) * EPB + (e)]

    const int tid  = threadIdx.x;
    const int lane = tid & 31;
    const int warp = tid >> 5;
    const int sub  = warp & 3;          // gate quarter
    const int kh   = warp >> 2;         // k half (0/1)
    const int ea   = lane + kh * 32;          // owned element (cell update)
    const int eb   = lane + (1 - kh) * 32;    // other element (matvec only)
    const int ba   = blockIdx.x * EPB + ea;
    const int bb   = blockIdx.x * EPB + eb;
    const int u0   = 5 * sub;
    const int kb   = kh * KH;
    const int ptnr = tid ^ 128;         // partner thread (other k half)

    // ---------------- stage weights ----------------
    {
        const float* Wsrc[3] = {Whh0, Wih1, Whh1};
        for (int idx = tid; idx < 3 * HID * 4 * 5; idx += NTHR) {
            int m = idx / (HID * 20);
            int r = idx % (HID * 20);
            int k = r / 20;
            int s = (r % 20) / 5;
            int q = r % 5;
            const float* W = Wsrc[m];
            float4 v;
            if (q < 4) {
                int g = 20 * q + 5 * s;
                v = make_float4(W[(g + 0) * HID + k], W[(g + 1) * HID + k],
                                W[(g + 2) * HID + k], W[(g + 3) * HID + k]);
            } else {
                int u = 5 * s + 4;
                v = make_float4(W[u * HID + k],        W[(20 + u) * HID + k],
                                W[(40 + u) * HID + k], W[(60 + u) * HID + k]);
            }
            SW(m, k, s, q) = v;
        }
        for (int idx = tid; idx < 2 * 4 * 5; idx += NTHR) {
            int i = idx / 20, s = (idx % 20) / 5, q = idx % 5;
            float4 v;
            if (q < 4) {
                int g = 20 * q + 5 * s;
                v = make_float4(Wih0[(g + 0) * 2 + i], Wih0[(g + 1) * 2 + i],
                                Wih0[(g + 2) * 2 + i], Wih0[(g + 3) * 2 + i]);
            } else {
                int u = 5 * s + 4;
                v = make_float4(Wih0[u * 2 + i],        Wih0[(20 + u) * 2 + i],
                                Wih0[(40 + u) * 2 + i], Wih0[(60 + u) * 2 + i]);
            }
            SWX(i, s, q) = v;
        }
        for (int idx = tid; idx < 2 * 4 * 5; idx += NTHR) {
            int l = idx / 20, s = (idx % 20) / 5, q = idx % 5;
            const float* bi = l ? bih1 : bih0;
            const float* bh = l ? bhh1 : bhh0;
            float4 v;
            if (q < 4) {
                int g = 20 * q + 5 * s;
                v = make_float4(bi[g] + bh[g],         bi[g + 1] + bh[g + 1],
                                bi[g + 2] + bh[g + 2], bi[g + 3] + bh[g + 3]);
            } else {
                int u = 5 * s + 4;
                v = make_float4(bi[u] + bh[u],           bi[20 + u] + bh[20 + u],
                                bi[40 + u] + bh[40 + u], bi[60 + u] + bh[60 + u]);
            }
            SBIAS(l, s, q) = v;
        }
    }

    // ---------------- init owned state ----------------
    float cA[5], cB[5], hA[5], hB[5];
#pragma unroll
    for (int j = 0; j < 5; j++) {
        int u = u0 + j;
        cA[j] = c0[(size_t)ba * HID + u];
        cB[j] = c0[(size_t)B * HID + (size_t)ba * HID + u];
        float h1 = h0[(size_t)ba * HID + u];
        float h2 = h0[(size_t)B * HID + (size_t)ba * HID + u];
        SH(0, ea, u) = pack2(h1, h1);
        SH(1, ea, u) = pack2(h2, h2);
    }
    __syncthreads();

    float lg0 = 0.f, lg1 = 0.f, lg2 = 0.f;   // decoder partials (owned elem, 5 units)
    const float2* x2 = reinterpret_cast<const float2*>(x);

#pragma unroll 1
    for (int t = 0; t < T_STEPS; t++) {
        ULL gpa[10], gpb[10];

        // ======== layer 1: partial matvec over this thread's k half ========
        if (kh == 0) {
            // bias + input projection assigned to k-half 0
            const ulonglong2* bbv = reinterpret_cast<const ulonglong2*>(&SBIAS(0, sub, 0));
#pragma unroll
            for (int q = 0; q < 5; q++) {
                gpa[2 * q] = bbv[q].x;  gpa[2 * q + 1] = bbv[q].y;
                gpb[2 * q] = bbv[q].x;  gpb[2 * q + 1] = bbv[q].y;
            }
            float2 xa = x2[(size_t)t * B + ba];
            float2 xb = x2[(size_t)t * B + bb];
            mv_accum2(gpa, gpb, pack2(xa.x, xa.x), pack2(xb.x, xb.x), &SWX(0, sub, 0));
            mv_accum2(gpa, gpb, pack2(xa.y, xa.y), pack2(xb.y, xb.y), &SWX(1, sub, 0));
        } else {
#pragma unroll
            for (int j = 0; j < 10; j++) { gpa[j] = 0ull; gpb[j] = 0ull; }
        }
#pragma unroll
        for (int k = 0; k < KH; k++)
            mv_accum2(gpa, gpb, SH(0, ea, kb + k), SH(0, eb, kb + k),
                      &SW(0, kb + k, sub, 0));

        // exchange: send other-element partial, receive owned-element partial
#pragma unroll
        for (int j = 0; j < 10; j++) SEX(tid, j) = gpb[j];
        __syncthreads();
#pragma unroll
        for (int j = 0; j < 10; j++) { ULL p = SEX(ptnr, j); ADD2(gpa[j], gpa[j], p); }

        cell_update(gpa, cA, hA);
#pragma unroll
        for (int j = 0; j < 5; j++) SH(0, ea, u0 + j) = pack2(hA[j], hA[j]);
        __syncthreads();

        // ======== layer 2: partial matvec (h1 new + h2 old) ========
        if (kh == 0) {
            const ulonglong2* bbv = reinterpret_cast<const ulonglong2*>(&SBIAS(1, sub, 0));
#pragma unroll
            for (int q = 0; q < 5; q++) {
                gpa[2 * q] = bbv[q].x;  gpa[2 * q + 1] = bbv[q].y;
                gpb[2 * q] = bbv[q].x;  gpb[2 * q + 1] = bbv[q].y;
            }
        } else {
#pragma unroll
            for (int j = 0; j < 10; j++) { gpa[j] = 0ull; gpb[j] = 0ull; }
        }
#pragma unroll
        for (int k = 0; k < KH; k++)
            mv_accum2(gpa, gpb, SH(0, ea, kb + k), SH(0, eb, kb + k),
                      &SW(1, kb + k, sub, 0));
#pragma unroll
        for (int k = 0; k < KH; k++)
            mv_accum2(gpa, gpb, SH(1, ea, kb + k), SH(1, eb, kb + k),
                      &SW(2, kb + k, sub, 0));

#pragma unroll
        for (int j = 0; j < 10; j++) SEX(tid, j) = gpb[j];
        __syncthreads();
#pragma unroll
        for (int j = 0; j < 10; j++) { ULL p = SEX(ptnr, j); ADD2(gpa[j], gpa[j], p); }

        cell_update(gpa, cB, hB);
#pragma unroll
        for (int j = 0; j < 5; j++) SH(1, ea, u0 + j) = pack2(hB[j], hB[j]);

        // ---- fused decoder partials (warp-uniform loads) ----
        const float* wd = Wdec + t * HID + u0;
#pragma unroll
        for (int j = 0; j < 5; j++) {
            lg0 = fmaf(hB[j], __ldg(wd + j),                     lg0);
            lg1 = fmaf(hB[j], __ldg(wd + T_STEPS * HID + j),     lg1);
            lg2 = fmaf(hB[j], __ldg(wd + 2 * T_STEPS * HID + j), lg2);
        }
        __syncthreads();   // protects SEX reuse + SH(1) ordering for next step
    }

    // ---------------- outputs (each thread: owned element, 5 units) ----------------
    float* o_h = out + 2 * (size_t)B;
    float* o_c = o_h + 2 * (size_t)B * HID;
#pragma unroll
    for (int j = 0; j < 5; j++) {
        int u = u0 + j;
        o_h[(size_t)ba * HID + u]                   = hA[j];
        o_h[(size_t)B * HID + (size_t)ba * HID + u] = hB[j];
        o_c[(size_t)ba * HID + u]                   = cA[j];
        o_c[(size_t)B * HID + (size_t)ba * HID + u] = cB[j];
    }

    // reduce decoder partials across the 4 subs
    SLG(0, sub, ea) = lg0;
    SLG(1, sub, ea) = lg1;
    SLG(2, sub, ea) = lg2;
    __syncthreads();

    if (tid < EPB) {
        const int e = tid;
        const int b = blockIdx.x * EPB + e;
        float logit0 = SLG(0, 0, e) + SLG(0, 1, e) + SLG(0, 2, e) + SLG(0, 3, e) + bdec[0];
        float logit1 = SLG(1, 0, e) + SLG(1, 1, e) + SLG(1, 2, e) + SLG(1, 3, e) + bdec[1];
        float logit2 = SLG(2, 0, e) + SLG(2, 1, e) + SLG(2, 2, e) + SLG(2, 3, e) + bdec[2];

        float m   = fmaxf(logit0, fmaxf(logit1, logit2));
        float lse = m + logf(expf(logit0 - m) + expf(logit1 - m) + expf(logit2 - m));

        const float tinyf = 1.17549435e-38f;
        float best = -1e30f, sel_logit = logit0;
        int act = 0;
#pragma unroll
        for (int a = 0; a < 3; a++) {
            unsigned bits = jax_random_bits_partitionable((unsigned)(b * 3 + a));
            float f  = __uint_as_float((bits >> 9) | 0x3f800000u) - 1.0f;
            float uu = fmaxf(tinyf, f + tinyf);
            float gmb = -logf(-logf(uu));
            float lgv = (a == 0) ? logit0 : (a == 1) ? logit1 : logit2;
            float v   = lgv + gmb;
            if (v > best) { best = v; act = a; sel_logit = lgv; }
        }
        out[b]     = (float)act;
        out[B + b] = sel_logit - lse;
    }
}

extern "C" void kernel_launch(void* const* d_in, const int* in_sizes, int n_in,
                              void* d_out, int out_size) {
    const float* x    = (const float*)d_in[0];
    const float* h0   = (const float*)d_in[1];
    const float* c0   = (const float*)d_in[2];
    const float* Wih0 = (const float*)d_in[3];
    const float* Whh0 = (const float*)d_in[4];
    const float* bih0 = (const float*)d_in[5];
    const float* bhh0 = (const float*)d_in[6];
    const float* Wih1 = (const float*)d_in[7];
    const float* Whh1 = (const float*)d_in[8];
    const float* bih1 = (const float*)d_in[9];
    const float* bhh1 = (const float*)d_in[10];
    const float* Wdec = (const float*)d_in[11];
    const float* bdec = (const float*)d_in[12];

    int B = in_sizes[0] / (T_STEPS * 2);   // x is [T, B, 2]

    cudaFuncSetAttribute(lstm_fused_kernel,
                         cudaFuncAttributeMaxDynamicSharedMemorySize, SMEM_TOTAL);

    dim3 grid(B / EPB), block(NTHR);
    lstm_fused_kernel<<<grid, block, SMEM_TOTAL>>>(
        x, h0, c0, Wih0, Whh0, bih0, bhh0,
        Wih1, Whh1, bih1, bhh1, Wdec, bdec,
        (float*)d_out, B);
}

// round 9
// speedup vs baseline: 1.0013x; 1.0013x over previous
#include <cuda_runtime.h>
#include <cstdint>

#define T_STEPS 200
#define HID     20
#define NTHR    256      // warps 0-3: layer-1 group (A); warps 4-7: layer-2 group (B)
#define EPB     64       // elements per block (2 per thread: lane, lane+32)

typedef unsigned long long ULL;

// ---------- packed f32x2 helpers (Blackwell FFMA2; PTX-only) ----------
#define FMA2(d, a, b, c) \
    asm("fma.rn.f32x2 %0, %1, %2, %3;" : "=l"(d) : "l"(a), "l"(b), "l"(c))

__device__ __forceinline__ ULL pack2(float x, float y) {
    ULL r;
    asm("mov.b64 %0, {%1, %2};" : "=l"(r)
        : "r"(__float_as_uint(x)), "r"(__float_as_uint(y)));
    return r;
}
__device__ __forceinline__ void unpack2(ULL v, float &x, float &y) {
    unsigned lo, hi;
    asm("mov.b64 {%0, %1}, %2;" : "=r"(lo), "=r"(hi) : "l"(v));
    x = __uint_as_float(lo);
    y = __uint_as_float(hi);
}

// ---------- fast activations (MUFU EX2+RCP, ~1e-6 rel err) ----------
__device__ __forceinline__ float sigm(float x) {
    return __fdividef(1.0f, 1.0f + __expf(-x));
}
__device__ __forceinline__ float tanh_fast(float x) {
    float ax = fabsf(x);
    float e  = __expf(-2.0f * ax);
    float r  = __fdividef(1.0f - e, 1.0f + e);
    return copysignf(r, x);
}

// ---------- exact JAX threefry2x32 (20 rounds) ----------
__device__ __forceinline__ void threefry2x32(unsigned k0, unsigned k1,
                                             unsigned x0, unsigned x1,
                                             unsigned &o0, unsigned &o1) {
    unsigned ks2 = k0 ^ k1 ^ 0x1BD11BDAu;
    x0 += k0; x1 += k1;
#define TFR(r) { x0 += x1; x1 = (x1 << r) | (x1 >> (32 - r)); x1 ^= x0; }
    TFR(13) TFR(15) TFR(26) TFR(6)
    x0 += k1;  x1 += ks2 + 1u;
    TFR(17) TFR(29) TFR(16) TFR(24)
    x0 += ks2; x1 += k0 + 2u;
    TFR(13) TFR(15) TFR(26) TFR(6)
    x0 += k0;  x1 += k1 + 3u;
    TFR(17) TFR(29) TFR(16) TFR(24)
    x0 += k1;  x1 += ks2 + 4u;
    TFR(13) TFR(15) TFR(26) TFR(6)
    x0 += ks2; x1 += k0 + 5u;
#undef TFR
    o0 = x0; o1 = x1;
}
// JAX partitionable threefry: ctr=(0,j), bits = o0^o1  (key (0,42))
__device__ __forceinline__ unsigned jax_random_bits_partitionable(unsigned j) {
    unsigned o0, o1;
    threefry2x32(0u, 42u, 0u, j, o0, o1);
    return o0 ^ o1;
}

// One k-contribution for two elements: 5 broadcast LDS.128 -> 20 FFMA2.
// h values arrive pre-duplicated as packed (h,h).
__device__ __forceinline__ void mv_accum2(ULL* gpa, ULL* gpb,
                                          ULL h2a, ULL h2b,
                                          const float4* __restrict__ wrow) {
    const ulonglong2* r = reinterpret_cast<const ulonglong2*>(wrow);
#pragma unroll
    for (int q = 0; q < 5; q++) {
        ulonglong2 w = r[q];
        FMA2(gpa[2 * q],     h2a, w.x, gpa[2 * q]);
        FMA2(gpa[2 * q + 1], h2a, w.y, gpa[2 * q + 1]);
        FMA2(gpb[2 * q],     h2b, w.x, gpb[2 * q]);
        FMA2(gpb[2 * q + 1], h2b, w.y, gpb[2 * q + 1]);
    }
}

// gp layout (units u0..u0+4): gp[2q],gp[2q+1] (q<4) = gate-group q for units
// (u0..u0+3); gp[8]=(i4,f4), gp[9]=(g4,o4) for unit u0+4
__device__ __forceinline__ void cell_update(ULL* gp, float* c, float* hout) {
    float iv[5], fv[5], gv[5], ov[5];
    unpack2(gp[0], iv[0], iv[1]); unpack2(gp[1], iv[2], iv[3]);
    unpack2(gp[2], fv[0], fv[1]); unpack2(gp[3], fv[2], fv[3]);
    unpack2(gp[4], gv[0], gv[1]); unpack2(gp[5], gv[2], gv[3]);
    unpack2(gp[6], ov[0], ov[1]); unpack2(gp[7], ov[2], ov[3]);
    unpack2(gp[8], iv[4], fv[4]);
    unpack2(gp[9], gv[4], ov[4]);
#pragma unroll
    for (int j = 0; j < 5; j++) {
        float cv = fmaf(sigm(fv[j]), c[j], sigm(iv[j]) * tanh_fast(gv[j]));
        c[j] = cv;
        hout[j] = sigm(ov[j]) * tanh_fast(cv);
    }
}

// dynamic shared layout (bytes)
#define OFF_SW    0                      // float4 [3][20][4][5]   = 19200
#define OFF_SWX   19200                  // float4 [2][4][5]       = 640
#define OFF_SBIAS 19840                  // float4 [2][4][5]       = 640
#define OFF_SHA   20480                  // ULL [2][64][21]        = 21504
#define OFF_SHB   41984                  // ULL [2][64][21]        = 21504
#define OFF_SLG   63488                  // float [3][4][64]       = 3072
#define SMEM_TOTAL 66560

__global__ void __launch_bounds__(NTHR, 2)
lstm_fused_kernel(const float* __restrict__ x,
                  const float* __restrict__ h0,
                  const float* __restrict__ c0,
                  const float* __restrict__ Wih0,
                  const float* __restrict__ Whh0,
                  const float* __restrict__ bih0,
                  const float* __restrict__ bhh0,
                  const float* __restrict__ Wih1,
                  const float* __restrict__ Whh1,
                  const float* __restrict__ bih1,
                  const float* __restrict__ bhh1,
                  const float* __restrict__ Wdec,
                  const float* __restrict__ bdec,
                  float* __restrict__ out,
                  int B) {
    extern __shared__ __align__(16) char dsm[];
    float4* sW    = reinterpret_cast<float4*>(dsm + OFF_SW);     // [m][k][sub][q]
    float4* sWx   = reinterpret_cast<float4*>(dsm + OFF_SWX);    // [i][sub][q]
    float4* sBias = reinterpret_cast<float4*>(dsm + OFF_SBIAS);  // [l][sub][q]
    ULL*    sHA   = reinterpret_cast<ULL*>(dsm + OFF_SHA);       // [buf][e][21] (h,h)
    ULL*    sHB   = reinterpret_cast<ULL*>(dsm + OFF_SHB);       // [buf][e][21] (h,h)
    float*  sLG   = reinterpret_cast<float*>(dsm + OFF_SLG);     // [a][sub][e]

#define SW(m, k, s, q) sW[(((m) * HID + (k)) * 4 + (s)) * 5 + (q)]
#define SWX(i, s, q)   sWx[((i) * 4 + (s)) * 5 + (q)]
#define SBIAS(l, s, q) sBias[((l) * 4 + (s)) * 5 + (q)]
#define SHA(bf, e, k)  sHA[((bf) * EPB + (e)) * 21 + (k)]
#define SHB(bf, e, k)  sHB[((bf) * EPB + (e)) * 21 + (k)]
#define SLG(a, s, e)   sLG[((a) * 4 + (s)) * EPB + (e)]

    const int tid  = threadIdx.x;
    const int lane = tid & 31;
    const int warp = tid >> 5;
    const bool grpA = (warp < 4);       // layer-1 group
    const int sub  = warp & 3;          // gate quarter within group
    const int e0   = lane;              // first element (block-local)
    const int e1   = lane + 32;         // second element
    const int b0   = blockIdx.x * EPB + e0;
    const int b1   = b0 + 32;
    const int u0   = 5 * sub;

    // ---------------- stage weights (all 256 threads) ----------------
    {
        const float* Wsrc[3] = {Whh0, Wih1, Whh1};
        for (int idx = tid; idx < 3 * HID * 4 * 5; idx += NTHR) {
            int m = idx / (HID * 20);
            int r = idx % (HID * 20);
            int k = r / 20;
            int s = (r % 20) / 5;
            int q = r % 5;
            const float* W = Wsrc[m];
            float4 v;
            if (q < 4) {
                int g = 20 * q + 5 * s;
                v = make_float4(W[(g + 0) * HID + k], W[(g + 1) * HID + k],
                                W[(g + 2) * HID + k], W[(g + 3) * HID + k]);
            } else {
                int u = 5 * s + 4;
                v = make_float4(W[u * HID + k],        W[(20 + u) * HID + k],
                                W[(40 + u) * HID + k], W[(60 + u) * HID + k]);
            }
            SW(m, k, s, q) = v;
        }
        for (int idx = tid; idx < 2 * 4 * 5; idx += NTHR) {
            int i = idx / 20, s = (idx % 20) / 5, q = idx % 5;
            float4 v;
            if (q < 4) {
                int g = 20 * q + 5 * s;
                v = make_float4(Wih0[(g + 0) * 2 + i], Wih0[(g + 1) * 2 + i],
                                Wih0[(g + 2) * 2 + i], Wih0[(g + 3) * 2 + i]);
            } else {
                int u = 5 * s + 4;
                v = make_float4(Wih0[u * 2 + i],        Wih0[(20 + u) * 2 + i],
                                Wih0[(40 + u) * 2 + i], Wih0[(60 + u) * 2 + i]);
            }
            SWX(i, s, q) = v;
        }
        for (int idx = tid; idx < 2 * 4 * 5; idx += NTHR) {
            int l = idx / 20, s = (idx % 20) / 5, q = idx % 5;
            const float* bi = l ? bih1 : bih0;
            const float* bh = l ? bhh1 : bhh0;
            float4 v;
            if (q < 4) {
                int g = 20 * q + 5 * s;
                v = make_float4(bi[g] + bh[g],         bi[g + 1] + bh[g + 1],
                                bi[g + 2] + bh[g + 2], bi[g + 3] + bh[g + 3]);
            } else {
                int u = 5 * s + 4;
                v = make_float4(bi[u] + bh[u],           bi[20 + u] + bh[20 + u],
                                bi[40 + u] + bh[40 + u], bi[60 + u] + bh[60 + u]);
            }
            SBIAS(l, s, q) = v;
        }
    }

    // ---------------- init state ----------------
    // Group A owns layer-1 state (c1, h1); group B owns layer-2 (c2, h2) + logits.
    float cS[2][5], hS[2][5];           // [elem][unit] for this group's layer
    float lg[2][3] = {{0.f, 0.f, 0.f}, {0.f, 0.f, 0.f}};
    if (grpA) {
#pragma unroll
        for (int j = 0; j < 5; j++) {
            int u = u0 + j;
            cS[0][j] = c0[(size_t)b0 * HID + u];
            cS[1][j] = c0[(size_t)b1 * HID + u];
            float ha0 = h0[(size_t)b0 * HID + u];
            float ha1 = h0[(size_t)b1 * HID + u];
            SHA(1, e0, u) = pack2(ha0, ha0);   // h1(-1) read at iter 0 (buf 0^1=1)
            SHA(1, e1, u) = pack2(ha1, ha1);
        }
    } else {
#pragma unroll
        for (int j = 0; j < 5; j++) {
            int u = u0 + j;
            cS[0][j] = c0[(size_t)B * HID + (size_t)b0 * HID + u];
            cS[1][j] = c0[(size_t)B * HID + (size_t)b1 * HID + u];
            float hb0 = h0[(size_t)B * HID + (size_t)b0 * HID + u];
            float hb1 = h0[(size_t)B * HID + (size_t)b1 * HID + u];
            SHB(0, e0, u) = pack2(hb0, hb0);   // h2(-1) read at iter 1 (buf 1^1=0)
            SHB(0, e1, u) = pack2(hb1, hb1);
        }
    }
    __syncthreads();

    const float2* x2 = reinterpret_cast<const float2*>(x);

    // Pipeline: iter i — group A computes layer-1 step i (i<T);
    //           group B computes layer-2 step i-1 (i>=1). One barrier per iter.
#pragma unroll 1
    for (int i = 0; i <= T_STEPS; i++) {
        const int p = i & 1;            // write buffer; reads come from p^1
        ULL gpa[10], gpb[10];

        if (grpA) {
            if (i < T_STEPS) {
                // bias + input projection
                const ulonglong2* bbv =
                    reinterpret_cast<const ulonglong2*>(&SBIAS(0, sub, 0));
#pragma unroll
                for (int q = 0; q < 5; q++) {
                    gpa[2 * q] = bbv[q].x;  gpa[2 * q + 1] = bbv[q].y;
                    gpb[2 * q] = bbv[q].x;  gpb[2 * q + 1] = bbv[q].y;
                }
                float2 xa = x2[(size_t)i * B + b0];
                float2 xb = x2[(size_t)i * B + b1];
                mv_accum2(gpa, gpb, pack2(xa.x, xa.x), pack2(xb.x, xb.x),
                          &SWX(0, sub, 0));
                mv_accum2(gpa, gpb, pack2(xa.y, xa.y), pack2(xb.y, xb.y),
                          &SWX(1, sub, 0));
                // recurrent matvec over h1(i-1)
#pragma unroll 5
                for (int k = 0; k < HID; k++)
                    mv_accum2(gpa, gpb, SHA(p ^ 1, e0, k), SHA(p ^ 1, e1, k),
                              &SW(0, k, sub, 0));
                cell_update(gpa, cS[0], hS[0]);
                cell_update(gpb, cS[1], hS[1]);
#pragma unroll
                for (int j = 0; j < 5; j++) {
                    SHA(p, e0, u0 + j) = pack2(hS[0][j], hS[0][j]);
                    SHA(p, e1, u0 + j) = pack2(hS[1][j], hS[1][j]);
                }
            }
        } else {
            if (i >= 1) {
                const int t = i - 1;
                const ulonglong2* bbv =
                    reinterpret_cast<const ulonglong2*>(&SBIAS(1, sub, 0));
#pragma unroll
                for (int q = 0; q < 5; q++) {
                    gpa[2 * q] = bbv[q].x;  gpa[2 * q + 1] = bbv[q].y;
                    gpb[2 * q] = bbv[q].x;  gpb[2 * q + 1] = bbv[q].y;
                }
                // input matvec over h1(t) = h1(i-1), in buffer (i-1)&1 = p^1
#pragma unroll 5
                for (int k = 0; k < HID; k++)
                    mv_accum2(gpa, gpb, SHA(p ^ 1, e0, k), SHA(p ^ 1, e1, k),
                              &SW(1, k, sub, 0));
                // recurrent matvec over h2(t-1), written at iter i-1 into p^1
#pragma unroll 5
                for (int k = 0; k < HID; k++)
                    mv_accum2(gpa, gpb, SHB(p ^ 1, e0, k), SHB(p ^ 1, e1, k),
                              &SW(2, k, sub, 0));
                cell_update(gpa, cS[0], hS[0]);
                cell_update(gpb, cS[1], hS[1]);
#pragma unroll
                for (int j = 0; j < 5; j++) {
                    SHB(p, e0, u0 + j) = pack2(hS[0][j], hS[0][j]);
                    SHB(p, e1, u0 + j) = pack2(hS[1][j], hS[1][j]);
                }
                // fused decoder partials (warp-uniform loads)
                const float* wd = Wdec + t * HID + u0;
#pragma unroll
                for (int j = 0; j < 5; j++) {
                    float w0 = __ldg(wd + j);
                    float w1 = __ldg(wd + T_STEPS * HID + j);
                    float w2 = __ldg(wd + 2 * T_STEPS * HID + j);
                    lg[0][0] = fmaf(hS[0][j], w0, lg[0][0]);
                    lg[0][1] = fmaf(hS[0][j], w1, lg[0][1]);
                    lg[0][2] = fmaf(hS[0][j], w2, lg[0][2]);
                    lg[1][0] = fmaf(hS[1][j], w0, lg[1][0]);
                    lg[1][1] = fmaf(hS[1][j], w1, lg[1][1]);
                    lg[1][2] = fmaf(hS[1][j], w2, lg[1][2]);
                }
            }
        }
        __syncthreads();
    }

    // ---------------- outputs ----------------
    float* o_h = out + 2 * (size_t)B;
    float* o_c = o_h + 2 * (size_t)B * HID;
    if (grpA) {
#pragma unroll
        for (int j = 0; j < 5; j++) {
            int u = u0 + j;
            o_h[(size_t)b0 * HID + u] = hS[0][j];
            o_h[(size_t)b1 * HID + u] = hS[1][j];
            o_c[(size_t)b0 * HID + u] = cS[0][j];
            o_c[(size_t)b1 * HID + u] = cS[1][j];
        }
    } else {
#pragma unroll
        for (int j = 0; j < 5; j++) {
            int u = u0 + j;
            o_h[(size_t)B * HID + (size_t)b0 * HID + u] = hS[0][j];
            o_h[(size_t)B * HID + (size_t)b1 * HID + u] = hS[1][j];
            o_c[(size_t)B * HID + (size_t)b0 * HID + u] = cS[0][j];
            o_c[(size_t)B * HID + (size_t)b1 * HID + u] = cS[1][j];
        }
        // stash decoder partials for reduction
#pragma unroll
        for (int a = 0; a < 3; a++) {
            SLG(a, sub, e0) = lg[0][a];
            SLG(a, sub, e1) = lg[1][a];
        }
    }
    __syncthreads();

    if (tid < EPB) {
        const int e = tid;
        const int b = blockIdx.x * EPB + e;
        float logit0 = SLG(0, 0, e) + SLG(0, 1, e) + SLG(0, 2, e) + SLG(0, 3, e) + bdec[0];
        float logit1 = SLG(1, 0, e) + SLG(1, 1, e) + SLG(1, 2, e) + SLG(1, 3, e) + bdec[1];
        float logit2 = SLG(2, 0, e) + SLG(2, 1, e) + SLG(2, 2, e) + SLG(2, 3, e) + bdec[2];

        float m   = fmaxf(logit0, fmaxf(logit1, logit2));
        float lse = m + logf(expf(logit0 - m) + expf(logit1 - m) + expf(logit2 - m));

        const float tinyf = 1.17549435e-38f;
        float best = -1e30f, sel_logit = logit0;
        int act = 0;
#pragma unroll
        for (int a = 0; a < 3; a++) {
            unsigned bits = jax_random_bits_partitionable((unsigned)(b * 3 + a));
            float f  = __uint_as_float((bits >> 9) | 0x3f800000u) - 1.0f;
            float uu = fmaxf(tinyf, f + tinyf);
            float gmb = -logf(-logf(uu));
            float lgv = (a == 0) ? logit0 : (a == 1) ? logit1 : logit2;
            float v   = lgv + gmb;
            if (v > best) { best = v; act = a; sel_logit = lgv; }
        }
        out[b]     = (float)act;
        out[B + b] = sel_logit - lse;
    }
}

extern "C" void kernel_launch(void* const* d_in, const int* in_sizes, int n_in,
                              void* d_out, int out_size) {
    const float* x    = (const float*)d_in[0];
    const float* h0   = (const float*)d_in[1];
    const float* c0   = (const float*)d_in[2];
    const float* Wih0 = (const float*)d_in[3];
    const float* Whh0 = (const float*)d_in[4];
    const float* bih0 = (const float*)d_in[5];
    const float* bhh0 = (const float*)d_in[6];
    const float* Wih1 = (const float*)d_in[7];
    const float* Whh1 = (const float*)d_in[8];
    const float* bih1 = (const float*)d_in[9];
    const float* bhh1 = (const float*)d_in[10];
    const float* Wdec = (const float*)d_in[11];
    const float* bdec = (const float*)d_in[12];

    int B = in_sizes[0] / (T_STEPS * 2);   // x is [T, B, 2]

    cudaFuncSetAttribute(lstm_fused_kernel,
                         cudaFuncAttributeMaxDynamicSharedMemorySize, SMEM_TOTAL);

    dim3 grid(B / EPB), block(NTHR);
    lstm_fused_kernel<<<grid, block, SMEM_TOTAL>>>(
        x, h0, c0, Wih0, Whh0, bih0, bhh0,
        Wih1, Whh1, bih1, bhh1, Wdec, bdec,
        (float*)d_out, B);
}

// round 10
// speedup vs baseline: 1.4577x; 1.4557x over previous
#include <cuda_runtime.h>
#include <cstdint>

#define T_STEPS 200
#define HID     20
#define NTHR    128      // 4 warps; warp = gate-quarter (sub), lane = element
#define EPB     64       // elements per block (2 per thread: lane, lane+32)

typedef unsigned long long ULL;

// ---------- packed f32x2 helpers (Blackwell FFMA2; PTX-only) ----------
#define FMA2(d, a, b, c) \
    asm("fma.rn.f32x2 %0, %1, %2, %3;" : "=l"(d) : "l"(a), "l"(b), "l"(c))
#define MUL2(d, a, b) \
    asm("mul.rn.f32x2 %0, %1, %2;" : "=l"(d) : "l"(a), "l"(b))

__device__ __forceinline__ ULL pack2(float x, float y) {
    ULL r;
    asm("mov.b64 %0, {%1, %2};" : "=l"(r)
        : "r"(__float_as_uint(x)), "r"(__float_as_uint(y)));
    return r;
}
__device__ __forceinline__ void unpack2(ULL v, float &x, float &y) {
    unsigned lo, hi;
    asm("mov.b64 {%0, %1}, %2;" : "=r"(lo), "=r"(hi) : "l"(v));
    x = __uint_as_float(lo);
    y = __uint_as_float(hi);
}
__device__ __forceinline__ float ex2(float x) {
    float r;
    asm("ex2.approx.f32 %0, %1;" : "=f"(r) : "f"(x));
    return r;
}

#define SMASK 0x8000000080000000ull
#define L2E_1 1.4426950f     // log2(e)
#define L2E_2 2.8853901f     // 2*log2(e)

// Core: given e0,e1 = exp2(-k|x|) per lane, return packed (1-e)/(1+e) >= 0.
// Division-free: d=1+e in (1,2]; linear seed + 3 packed Newton iters (~2e-10 rel).
#define TCORE(res, e0, e1) do {                                     \
    ULL _ep = pack2((e0), (e1)), _np, _nd, _r, _tt;                 \
    FMA2(_np, _ep, K_M1, K_P1);      /* 1 - e          */           \
    FMA2(_nd, _ep, K_M1, K_M1);      /* -(1 + e)       */           \
    FMA2(_r,  _nd, K_H,  K_SEED);    /* 1.4571 - 0.5d  */           \
    FMA2(_tt, _nd, _r, K_P1); FMA2(_r, _r, _tt, _r);                \
    FMA2(_tt, _nd, _r, K_P1); FMA2(_r, _r, _tt, _r);                \
    FMA2(_tt, _nd, _r, K_P1); FMA2(_r, _r, _tt, _r);                \
    MUL2(res, _np, _r);                                             \
} while (0)

// Packed sigmoid on a gate pair: sigm(x) = 0.5 + 0.5*sign(x)*tanh(|x|/2)
#define SIGM2(res, xp) do {                                         \
    float _x0, _x1; unpack2((xp), _x0, _x1);                        \
    float _e0 = ex2(-L2E_1 * fabsf(_x0));                           \
    float _e1 = ex2(-L2E_1 * fabsf(_x1));                           \
    ULL _tc; TCORE(_tc, _e0, _e1);                                  \
    _tc |= ((xp) & SMASK);                                          \
    FMA2(res, _tc, K_H, K_H);                                       \
} while (0)

// Packed tanh on a pair
#define TANH2(res, xp) do {                                         \
    float _x0, _x1; unpack2((xp), _x0, _x1);                        \
    float _e0 = ex2(-L2E_2 * fabsf(_x0));                           \
    float _e1 = ex2(-L2E_2 * fabsf(_x1));                           \
    ULL _tc; TCORE(_tc, _e0, _e1);                                  \
    res = _tc | ((xp) & SMASK);                                     \
} while (0)

// ---------- exact JAX threefry2x32 (20 rounds) ----------
__device__ __forceinline__ void threefry2x32(unsigned k0, unsigned k1,
                                             unsigned x0, unsigned x1,
                                             unsigned &o0, unsigned &o1) {
    unsigned ks2 = k0 ^ k1 ^ 0x1BD11BDAu;
    x0 += k0; x1 += k1;
#define TFR(r) { x0 += x1; x1 = (x1 << r) | (x1 >> (32 - r)); x1 ^= x0; }
    TFR(13) TFR(15) TFR(26) TFR(6)
    x0 += k1;  x1 += ks2 + 1u;
    TFR(17) TFR(29) TFR(16) TFR(24)
    x0 += ks2; x1 += k0 + 2u;
    TFR(13) TFR(15) TFR(26) TFR(6)
    x0 += k0;  x1 += k1 + 3u;
    TFR(17) TFR(29) TFR(16) TFR(24)
    x0 += k1;  x1 += ks2 + 4u;
    TFR(13) TFR(15) TFR(26) TFR(6)
    x0 += ks2; x1 += k0 + 5u;
#undef TFR
    o0 = x0; o1 = x1;
}
// JAX partitionable threefry: ctr=(0,j), bits = o0^o1  (key (0,42))
__device__ __forceinline__ unsigned jax_random_bits_partitionable(unsigned j) {
    unsigned o0, o1;
    threefry2x32(0u, 42u, 0u, j, o0, o1);
    return o0 ^ o1;
}

// One k-contribution for two elements: 5 broadcast LDS.128 -> 20 FFMA2.
// h arrives pre-duplicated as packed (h,h) from shared.
__device__ __forceinline__ void mv_accum2(ULL* gpa, ULL* gpb,
                                          ULL h2a, ULL h2b,
                                          const float4* __restrict__ wrow) {
    const ulonglong2* r = reinterpret_cast<const ulonglong2*>(wrow);
#pragma unroll
    for (int q = 0; q < 5; q++) {
        ulonglong2 w = r[q];
        FMA2(gpa[2 * q],     h2a, w.x, gpa[2 * q]);
        FMA2(gpa[2 * q + 1], h2a, w.y, gpa[2 * q + 1]);
        FMA2(gpb[2 * q],     h2b, w.x, gpb[2 * q]);
        FMA2(gpb[2 * q + 1], h2b, w.y, gpb[2 * q + 1]);
    }
}

// dynamic shared layout (bytes)
#define OFF_SW    0                      // float4 [3][20][4][5]   = 19200
#define OFF_SWX   19200                  // float4 [2][4][5]       = 640
#define OFF_SBIAS 19840                  // float4 [2][4][5]       = 640
#define OFF_SHA   20480                  // ULL [2][20][64]        = 20480
#define OFF_SHB   40960                  // ULL [2][20][64]        = 20480
#define OFF_SLG   61440                  // float [3][4][64]       = 3072
#define SMEM_TOTAL 64512

__global__ void __launch_bounds__(NTHR, 2)
lstm_fused_kernel(const float* __restrict__ x,
                  const float* __restrict__ h0,
                  const float* __restrict__ c0,
                  const float* __restrict__ Wih0,
                  const float* __restrict__ Whh0,
                  const float* __restrict__ bih0,
                  const float* __restrict__ bhh0,
                  const float* __restrict__ Wih1,
                  const float* __restrict__ Whh1,
                  const float* __restrict__ bih1,
                  const float* __restrict__ bhh1,
                  const float* __restrict__ Wdec,
                  const float* __restrict__ bdec,
                  float* __restrict__ out,
                  int B) {
    extern __shared__ __align__(16) char dsm[];
    float4* sW    = reinterpret_cast<float4*>(dsm + OFF_SW);
    float4* sWx   = reinterpret_cast<float4*>(dsm + OFF_SWX);
    float4* sBias = reinterpret_cast<float4*>(dsm + OFF_SBIAS);
    ULL*    sHA   = reinterpret_cast<ULL*>(dsm + OFF_SHA);   // [buf][k][e] (h,h)
    ULL*    sHB   = reinterpret_cast<ULL*>(dsm + OFF_SHB);   // [buf][k][e] (h,h)
    float*  sLG   = reinterpret_cast<float*>(dsm + OFF_SLG); // [a][sub][e]

#define SW(m, k, s, q) sW[(((m) * HID + (k)) * 4 + (s)) * 5 + (q)]
#define SWX(i, s, q)   sWx[((i) * 4 + (s)) * 5 + (q)]
#define SBIAS(l, s, q) sBias[((l) * 4 + (s)) * 5 + (q)]
#define SHA(bf, k, e)  sHA[((bf) * HID + (k)) * EPB + (e)]
#define SHB(bf, k, e)  sHB[((bf) * HID + (k)) * EPB + (e)]
#define SLG(a, s, e)   sLG[((a) * 4 + (s)) * EPB + (e)]

    // runtime-built packed constants (hoisted once)
    const ULL K_P1   = pack2(1.0f, 1.0f);
    const ULL K_M1   = pack2(-1.0f, -1.0f);
    const ULL K_H    = pack2(0.5f, 0.5f);
    const ULL K_SEED = pack2(1.4571072f, 1.4571072f);

    const int tid = threadIdx.x;
    const int sub = tid >> 5;           // warp id = gate quarter
    const int e0  = tid & 31;           // lane = first element
    const int e1  = e0 + 32;
    const int b0  = blockIdx.x * EPB + e0;
    const int b1  = b0 + 32;
    const int u0  = 5 * sub;

    // ---------------- stage weights ----------------
    {
        const float* Wsrc[3] = {Whh0, Wih1, Whh1};
        for (int idx = tid; idx < 3 * HID * 4 * 5; idx += NTHR) {
            int m = idx / (HID * 20);
            int r = idx % (HID * 20);
            int k = r / 20;
            int s = (r % 20) / 5;
            int q = r % 5;
            const float* W = Wsrc[m];
            float4 v;
            if (q < 4) {
                int g = 20 * q + 5 * s;
                v = make_float4(W[(g + 0) * HID + k], W[(g + 1) * HID + k],
                                W[(g + 2) * HID + k], W[(g + 3) * HID + k]);
            } else {
                int u = 5 * s + 4;
                v = make_float4(W[u * HID + k],        W[(20 + u) * HID + k],
                                W[(40 + u) * HID + k], W[(60 + u) * HID + k]);
            }
            SW(m, k, s, q) = v;
        }
        for (int idx = tid; idx < 2 * 4 * 5; idx += NTHR) {
            int i = idx / 20, s = (idx % 20) / 5, q = idx % 5;
            float4 v;
            if (q < 4) {
                int g = 20 * q + 5 * s;
                v = make_float4(Wih0[(g + 0) * 2 + i], Wih0[(g + 1) * 2 + i],
                                Wih0[(g + 2) * 2 + i], Wih0[(g + 3) * 2 + i]);
            } else {
                int u = 5 * s + 4;
                v = make_float4(Wih0[u * 2 + i],        Wih0[(20 + u) * 2 + i],
                                Wih0[(40 + u) * 2 + i], Wih0[(60 + u) * 2 + i]);
            }
            SWX(i, s, q) = v;
        }
        for (int idx = tid; idx < 2 * 4 * 5; idx += NTHR) {
            int l = idx / 20, s = (idx % 20) / 5, q = idx % 5;
            const float* bi = l ? bih1 : bih0;
            const float* bh = l ? bhh1 : bhh0;
            float4 v;
            if (q < 4) {
                int g = 20 * q + 5 * s;
                v = make_float4(bi[g] + bh[g],         bi[g + 1] + bh[g + 1],
                                bi[g + 2] + bh[g + 2], bi[g + 3] + bh[g + 3]);
            } else {
                int u = 5 * s + 4;
                v = make_float4(bi[u] + bh[u],           bi[20 + u] + bh[20 + u],
                                bi[40 + u] + bh[40 + u], bi[60 + u] + bh[60 + u]);
            }
            SBIAS(l, s, q) = v;
        }
    }

    // ---------------- init state ----------------
    // c packed per element per layer: pairs (u0,u0+1),(u0+2,u0+3) + scalar u0+4
    ULL cA01[2], cA23[2], cB01[2], cB23[2];
    float cA4[2], cB4[2];
    float hAo[2][5], hBo[2][5];
#pragma unroll
    for (int ei = 0; ei < 2; ei++) {
        int b = (ei == 0) ? b0 : b1;
        int e = (ei == 0) ? e0 : e1;
        cA01[ei] = pack2(c0[(size_t)b * HID + u0],     c0[(size_t)b * HID + u0 + 1]);
        cA23[ei] = pack2(c0[(size_t)b * HID + u0 + 2], c0[(size_t)b * HID + u0 + 3]);
        cA4[ei]  = c0[(size_t)b * HID + u0 + 4];
        const float* c1p = c0 + (size_t)B * HID + (size_t)b * HID;
        cB01[ei] = pack2(c1p[u0], c1p[u0 + 1]);
        cB23[ei] = pack2(c1p[u0 + 2], c1p[u0 + 3]);
        cB4[ei]  = c1p[u0 + 4];
#pragma unroll
        for (int j = 0; j < 5; j++) {
            float ha = h0[(size_t)b * HID + u0 + j];
            float hb = h0[(size_t)B * HID + (size_t)b * HID + u0 + j];
            SHA(0, u0 + j, e) = pack2(ha, ha);
            SHB(0, u0 + j, e) = pack2(hb, hb);
        }
    }
    __syncthreads();

    float lg[2][3] = {{0.f, 0.f, 0.f}, {0.f, 0.f, 0.f}};
    const float2* x2 = reinterpret_cast<const float2*>(x);

#pragma unroll 1
    for (int t = 0; t < T_STEPS; t++) {
        const int cur = t & 1, nxt = cur ^ 1;
        float2 xv0 = x2[(size_t)t * B + b0];
        float2 xv1 = x2[(size_t)t * B + b1];
        ULL gpa[10], gpb[10];

        // ---- layer 1: bias + input proj + recurrent matvec ----
        {
            const ulonglong2* bb = reinterpret_cast<const ulonglong2*>(&SBIAS(0, sub, 0));
#pragma unroll
            for (int q = 0; q < 5; q++) {
                gpa[2 * q] = bb[q].x;  gpa[2 * q + 1] = bb[q].y;
                gpb[2 * q] = bb[q].x;  gpb[2 * q + 1] = bb[q].y;
            }
        }
        mv_accum2(gpa, gpb, pack2(xv0.x, xv0.x), pack2(xv1.x, xv1.x), &SWX(0, sub, 0));
        mv_accum2(gpa, gpb, pack2(xv0.y, xv0.y), pack2(xv1.y, xv1.y), &SWX(1, sub, 0));
#pragma unroll 5
        for (int k = 0; k < HID; k++)
            mv_accum2(gpa, gpb, SHA(cur, k, e0), SHA(cur, k, e1), &SW(0, k, sub, 0));

        // ---- layer 1 cell update (packed activations) ----
        {
            float so4[2];
#pragma unroll
            for (int ei = 0; ei < 2; ei++) {
                ULL* gp = (ei == 0) ? gpa : gpb;
                ULL si, sf, tg, so, ig, tc, hp;
                // pair 01
                SIGM2(si, gp[0]); SIGM2(sf, gp[2]); TANH2(tg, gp[4]); SIGM2(so, gp[6]);
                MUL2(ig, si, tg);
                FMA2(cA01[ei], sf, cA01[ei], ig);
                TANH2(tc, cA01[ei]);
                MUL2(hp, so, tc);
                unpack2(hp, hAo[ei][0], hAo[ei][1]);
                // pair 23
                SIGM2(si, gp[1]); SIGM2(sf, gp[3]); TANH2(tg, gp[5]); SIGM2(so, gp[7]);
                MUL2(ig, si, tg);
                FMA2(cA23[ei], sf, cA23[ei], ig);
                TANH2(tc, cA23[ei]);
                MUL2(hp, so, tc);
                unpack2(hp, hAo[ei][2], hAo[ei][3]);
                // unit 4: gp[8]=(i4,f4) both sigm; gp[9]=(g4,o4) tanh/sigm mixed
                ULL s8; SIGM2(s8, gp[8]);
                float si4, sf4; unpack2(s8, si4, sf4);
                float g4, o4; unpack2(gp[9], g4, o4);
                float eg = ex2(-L2E_2 * fabsf(g4));
                float eo = ex2(-L2E_1 * fabsf(o4));
                ULL m; TCORE(m, eg, eo);
                m |= (gp[9] & SMASK);
                float tg4, to4; unpack2(m, tg4, to4);
                so4[ei] = fmaf(to4, 0.5f, 0.5f);
                float* c4 = (ei == 0) ? &cA4[0] : &cA4[1];
                *c4 = fmaf(sf4, *c4, si4 * tg4);
            }
            // paired tanh(c4) across elements
            float ea = ex2(-L2E_2 * fabsf(cA4[0]));
            float eb = ex2(-L2E_2 * fabsf(cA4[1]));
            ULL t4; TCORE(t4, ea, eb);
            float t4a, t4b; unpack2(t4, t4a, t4b);
            hAo[0][4] = so4[0] * copysignf(t4a, cA4[0]);
            hAo[1][4] = so4[1] * copysignf(t4b, cA4[1]);
        }
#pragma unroll
        for (int j = 0; j < 5; j++) {
            SHA(nxt, u0 + j, e0) = pack2(hAo[0][j], hAo[0][j]);
            SHA(nxt, u0 + j, e1) = pack2(hAo[1][j], hAo[1][j]);
        }
        __syncthreads();

        // ---- layer 2: bias + input(h1) matvec + recurrent matvec ----
        {
            const ulonglong2* bb = reinterpret_cast<const ulonglong2*>(&SBIAS(1, sub, 0));
#pragma unroll
            for (int q = 0; q < 5; q++) {
                gpa[2 * q] = bb[q].x;  gpa[2 * q + 1] = bb[q].y;
                gpb[2 * q] = bb[q].x;  gpb[2 * q + 1] = bb[q].y;
            }
        }
#pragma unroll 5
        for (int k = 0; k < HID; k++)
            mv_accum2(gpa, gpb, SHA(nxt, k, e0), SHA(nxt, k, e1), &SW(1, k, sub, 0));
#pragma unroll 5
        for (int k = 0; k < HID; k++)
            mv_accum2(gpa, gpb, SHB(cur, k, e0), SHB(cur, k, e1), &SW(2, k, sub, 0));

        // ---- layer 2 cell update ----
        {
            float so4[2];
#pragma unroll
            for (int ei = 0; ei < 2; ei++) {
                ULL* gp = (ei == 0) ? gpa : gpb;
                ULL si, sf, tg, so, ig, tc, hp;
                SIGM2(si, gp[0]); SIGM2(sf, gp[2]); TANH2(tg, gp[4]); SIGM2(so, gp[6]);
                MUL2(ig, si, tg);
                FMA2(cB01[ei], sf, cB01[ei], ig);
                TANH2(tc, cB01[ei]);
                MUL2(hp, so, tc);
                unpack2(hp, hBo[ei][0], hBo[ei][1]);
                SIGM2(si, gp[1]); SIGM2(sf, gp[3]); TANH2(tg, gp[5]); SIGM2(so, gp[7]);
                MUL2(ig, si, tg);
                FMA2(cB23[ei], sf, cB23[ei], ig);
                TANH2(tc, cB23[ei]);
                MUL2(hp, so, tc);
                unpack2(hp, hBo[ei][2], hBo[ei][3]);
                ULL s8; SIGM2(s8, gp[8]);
                float si4, sf4; unpack2(s8, si4, sf4);
                float g4, o4; unpack2(gp[9], g4, o4);
                float eg = ex2(-L2E_2 * fabsf(g4));
                float eo = ex2(-L2E_1 * fabsf(o4));
                ULL m; TCORE(m, eg, eo);
                m |= (gp[9] & SMASK);
                float tg4, to4; unpack2(m, tg4, to4);
                so4[ei] = fmaf(to4, 0.5f, 0.5f);
                float* c4 = (ei == 0) ? &cB4[0] : &cB4[1];
                *c4 = fmaf(sf4, *c4, si4 * tg4);
            }
            float ea = ex2(-L2E_2 * fabsf(cB4[0]));
            float eb = ex2(-L2E_2 * fabsf(cB4[1]));
            ULL t4; TCORE(t4, ea, eb);
            float t4a, t4b; unpack2(t4, t4a, t4b);
            hBo[0][4] = so4[0] * copysignf(t4a, cB4[0]);
            hBo[1][4] = so4[1] * copysignf(t4b, cB4[1]);
        }
#pragma unroll
        for (int j = 0; j < 5; j++) {
            SHB(nxt, u0 + j, e0) = pack2(hBo[0][j], hBo[0][j]);
            SHB(nxt, u0 + j, e1) = pack2(hBo[1][j], hBo[1][j]);
        }

        // ---- fused decoder partials (warp-uniform loads serve both elements) ----
        const float* wd = Wdec + t * HID + u0;
#pragma unroll
        for (int j = 0; j < 5; j++) {
            float w0 = __ldg(wd + j);
            float w1 = __ldg(wd + T_STEPS * HID + j);
            float w2 = __ldg(wd + 2 * T_STEPS * HID + j);
            lg[0][0] = fmaf(hBo[0][j], w0, lg[0][0]);
            lg[0][1] = fmaf(hBo[0][j], w1, lg[0][1]);
            lg[0][2] = fmaf(hBo[0][j], w2, lg[0][2]);
            lg[1][0] = fmaf(hBo[1][j], w0, lg[1][0]);
            lg[1][1] = fmaf(hBo[1][j], w1, lg[1][1]);
            lg[1][2] = fmaf(hBo[1][j], w2, lg[1][2]);
        }
        __syncthreads();
    }

    // ---------------- outputs ----------------
    float* o_h = out + 2 * (size_t)B;
    float* o_c = o_h + 2 * (size_t)B * HID;
#pragma unroll
    for (int ei = 0; ei < 2; ei++) {
        int b = (ei == 0) ? b0 : b1;
        float ca[5], cb[5];
        unpack2(cA01[ei], ca[0], ca[1]); unpack2(cA23[ei], ca[2], ca[3]); ca[4] = cA4[ei];
        unpack2(cB01[ei], cb[0], cb[1]); unpack2(cB23[ei], cb[2], cb[3]); cb[4] = cB4[ei];
#pragma unroll
        for (int j = 0; j < 5; j++) {
            int u = u0 + j;
            o_h[(size_t)b * HID + u]                   = hAo[ei][j];
            o_h[(size_t)B * HID + (size_t)b * HID + u] = hBo[ei][j];
            o_c[(size_t)b * HID + u]                   = ca[j];
            o_c[(size_t)B * HID + (size_t)b * HID + u] = cb[j];
        }
    }

    // reduce decoder partials across the 4 warps
#pragma unroll
    for (int a = 0; a < 3; a++) {
        SLG(a, sub, e0) = lg[0][a];
        SLG(a, sub, e1) = lg[1][a];
    }
    __syncthreads();

    if (sub == 0) {
#pragma unroll
        for (int ei = 0; ei < 2; ei++) {
            int e = (ei == 0) ? e0 : e1;
            int b = (ei == 0) ? b0 : b1;
            float logit0 = SLG(0, 0, e) + SLG(0, 1, e) + SLG(0, 2, e) + SLG(0, 3, e) + bdec[0];
            float logit1 = SLG(1, 0, e) + SLG(1, 1, e) + SLG(1, 2, e) + SLG(1, 3, e) + bdec[1];
            float logit2 = SLG(2, 0, e) + SLG(2, 1, e) + SLG(2, 2, e) + SLG(2, 3, e) + bdec[2];

            float m   = fmaxf(logit0, fmaxf(logit1, logit2));
            float lse = m + logf(expf(logit0 - m) + expf(logit1 - m) + expf(logit2 - m));

            const float tinyf = 1.17549435e-38f;
            float best = -1e30f, sel_logit = logit0;
            int act = 0;
#pragma unroll
            for (int a = 0; a < 3; a++) {
                unsigned bits = jax_random_bits_partitionable((unsigned)(b * 3 + a));
                float f  = __uint_as_float((bits >> 9) | 0x3f800000u) - 1.0f;
                float uu = fmaxf(tinyf, f + tinyf);
                float gmb = -logf(-logf(uu));
                float lgv = (a == 0) ? logit0 : (a == 1) ? logit1 : logit2;
                float v   = lgv + gmb;
                if (v > best) { best = v; act = a; sel_logit = lgv; }
            }
            out[b]     = (float)act;
            out[B + b] = sel_logit - lse;
        }
    }
}

extern "C" void kernel_launch(void* const* d_in, const int* in_sizes, int n_in,
                              void* d_out, int out_size) {
    const float* x    = (const float*)d_in[0];
    const float* h0   = (const float*)d_in[1];
    const float* c0   = (const float*)d_in[2];
    const float* Wih0 = (const float*)d_in[3];
    const float* Whh0 = (const float*)d_in[4];
    const float* bih0 = (const float*)d_in[5];
    const float* bhh0 = (const float*)d_in[6];
    const float* Wih1 = (const float*)d_in[7];
    const float* Whh1 = (const float*)d_in[8];
    const float* bih1 = (const float*)d_in[9];
    const float* bhh1 = (const float*)d_in[10];
    const float* Wdec = (const float*)d_in[11];
    const float* bdec = (const float*)d_in[12];

    int B = in_sizes[0] / (T_STEPS * 2);   // x is [T, B, 2]

    cudaFuncSetAttribute(lstm_fused_kernel,
                         cudaFuncAttributeMaxDynamicSharedMemorySize, SMEM_TOTAL);

    dim3 grid(B / EPB), block(NTHR);
    lstm_fused_kernel<<<grid, block, SMEM_TOTAL>>>(
        x, h0, c0, Wih0, Whh0, bih0, bhh0,
        Wih1, Whh1, bih1, bhh1, Wdec, bdec,
        (float*)d_out, B);
}

// round 12
// speedup vs baseline: 1.7842x; 1.2240x over previous
#include <cuda_runtime.h>
#include <cstdint>

#define T_STEPS 200
#define HID     20
#define NTHR    128      // 4 warps; warp = gate-quarter (sub), lane = element
#define EPB     64       // elements per block (2 per thread: lane, lane+32)
#define HPAD    21       // padded hidden stride (coprime with 32 -> conflict-free)

typedef unsigned long long ULL;

// ---------- packed f32x2 helpers (Blackwell FFMA2; PTX-only) ----------
#define FMA2(d, a, b, c) \
    asm("fma.rn.f32x2 %0, %1, %2, %3;" : "=l"(d) : "l"(a), "l"(b), "l"(c))

__device__ __forceinline__ ULL pack2(float x, float y) {
    ULL r;
    asm("mov.b64 %0, {%1, %2};" : "=l"(r)
        : "r"(__float_as_uint(x)), "r"(__float_as_uint(y)));
    return r;
}
__device__ __forceinline__ void unpack2(ULL v, float &x, float &y) {
    unsigned lo, hi;
    asm("mov.b64 {%0, %1}, %2;" : "=r"(lo), "=r"(hi) : "l"(v));
    x = __uint_as_float(lo);
    y = __uint_as_float(hi);
}

// ---------- fast activations (MUFU EX2+RCP, ~1e-6 rel err) ----------
__device__ __forceinline__ float sigm(float x) {
    return __fdividef(1.0f, 1.0f + __expf(-x));
}
__device__ __forceinline__ float tanh_fast(float x) {
    float ax = fabsf(x);
    float e  = __expf(-2.0f * ax);
    float r  = __fdividef(1.0f - e, 1.0f + e);
    return copysignf(r, x);
}

// ---------- exact JAX threefry2x32 (20 rounds) ----------
__device__ __forceinline__ void threefry2x32(unsigned k0, unsigned k1,
                                             unsigned x0, unsigned x1,
                                             unsigned &o0, unsigned &o1) {
    unsigned ks2 = k0 ^ k1 ^ 0x1BD11BDAu;
    x0 += k0; x1 += k1;
#define TFR(r) { x0 += x1; x1 = (x1 << r) | (x1 >> (32 - r)); x1 ^= x0; }
    TFR(13) TFR(15) TFR(26) TFR(6)
    x0 += k1;  x1 += ks2 + 1u;
    TFR(17) TFR(29) TFR(16) TFR(24)
    x0 += ks2; x1 += k0 + 2u;
    TFR(13) TFR(15) TFR(26) TFR(6)
    x0 += k0;  x1 += k1 + 3u;
    TFR(17) TFR(29) TFR(16) TFR(24)
    x0 += k1;  x1 += ks2 + 4u;
    TFR(13) TFR(15) TFR(26) TFR(6)
    x0 += ks2; x1 += k0 + 5u;
#undef TFR
    o0 = x0; o1 = x1;
}
// JAX partitionable threefry: ctr=(0,j), bits = o0^o1  (key (0,42))
__device__ __forceinline__ unsigned jax_random_bits_partitionable(unsigned j) {
    unsigned o0, o1;
    threefry2x32(0u, 42u, 0u, j, o0, o1);
    return o0 ^ o1;
}

// One k-contribution for two elements: 5 broadcast LDS.128 -> 20 FFMA2.
__device__ __forceinline__ void mv_accum2(ULL* gpa, ULL* gpb,
                                          float ha, float hb,
                                          const float4* __restrict__ wrow) {
    ULL h2a = pack2(ha, ha);
    ULL h2b = pack2(hb, hb);
    const ulonglong2* r = reinterpret_cast<const ulonglong2*>(wrow);
#pragma unroll
    for (int q = 0; q < 5; q++) {
        ulonglong2 w = r[q];
        FMA2(gpa[2 * q],     h2a, w.x, gpa[2 * q]);
        FMA2(gpa[2 * q + 1], h2a, w.y, gpa[2 * q + 1]);
        FMA2(gpb[2 * q],     h2b, w.x, gpb[2 * q]);
        FMA2(gpb[2 * q + 1], h2b, w.y, gpb[2 * q + 1]);
    }
}

// gp layout (units u0..u0+4): gp[2q],gp[2q+1] (q<4) = gate-group q for units
// (u0..u0+3); gp[8]=(i4,f4), gp[9]=(g4,o4) for unit u0+4
__device__ __forceinline__ void cell_update(ULL* gp, float* c, float* hout) {
    float iv[5], fv[5], gv[5], ov[5];
    unpack2(gp[0], iv[0], iv[1]); unpack2(gp[1], iv[2], iv[3]);
    unpack2(gp[2], fv[0], fv[1]); unpack2(gp[3], fv[2], fv[3]);
    unpack2(gp[4], gv[0], gv[1]); unpack2(gp[5], gv[2], gv[3]);
    unpack2(gp[6], ov[0], ov[1]); unpack2(gp[7], ov[2], ov[3]);
    unpack2(gp[8], iv[4], fv[4]);
    unpack2(gp[9], gv[4], ov[4]);
#pragma unroll
    for (int j = 0; j < 5; j++) {
        float cv = fmaf(sigm(fv[j]), c[j], sigm(iv[j]) * tanh_fast(gv[j]));
        c[j] = cv;
        hout[j] = sigm(ov[j]) * tanh_fast(cv);
    }
}

__global__ void __launch_bounds__(NTHR, 2)
lstm_fused_kernel(const float* __restrict__ x,
                  const float* __restrict__ h0,
                  const float* __restrict__ c0,
                  const float* __restrict__ Wih0,
                  const float* __restrict__ Whh0,
                  const float* __restrict__ bih0,
                  const float* __restrict__ bhh0,
                  const float* __restrict__ Wih1,
                  const float* __restrict__ Whh1,
                  const float* __restrict__ bih1,
                  const float* __restrict__ bhh1,
                  const float* __restrict__ Wdec,
                  const float* __restrict__ bdec,
                  float* __restrict__ out,
                  int B) {
    // sW[m][k][sub][q]: m=0 Whh0, m=1 Wih1, m=2 Whh1 (gate-permuted float4 packs)
    __shared__ float4 sW[3][HID][4][5];
    __shared__ float4 sWx[2][4][5];        // Wih0 columns 0/1
    __shared__ float4 sBias[2][4][5];      // combined biases per layer
    __shared__ float  sHA[2][EPB][HPAD];   // double-buffered layer-1 h
    __shared__ float  sHB[2][EPB][HPAD];   // double-buffered layer-2 h
    __shared__ float  sLG[3][4][EPB];      // decoder partial reduction scratch

    const int tid = threadIdx.x;
    const int sub = tid >> 5;           // warp id = gate quarter
    const int e0  = tid & 31;           // lane = first element
    const int e1  = e0 + 32;            // second element
    const int b0  = blockIdx.x * EPB + e0;
    const int b1  = b0 + 32;
    const int u0  = 5 * sub;

    // ---------------- stage weights ----------------
    {
        const float* Wsrc[3] = {Whh0, Wih1, Whh1};
        for (int idx = tid; idx < 3 * HID * 4 * 5; idx += NTHR) {
            int m = idx / (HID * 20);
            int r = idx % (HID * 20);
            int k = r / 20;
            int s = (r % 20) / 5;
            int q = r % 5;
            const float* W = Wsrc[m];
            float4 v;
            if (q < 4) {
                int g = 20 * q + 5 * s;
                v = make_float4(W[(g + 0) * HID + k], W[(g + 1) * HID + k],
                                W[(g + 2) * HID + k], W[(g + 3) * HID + k]);
            } else {
                int u = 5 * s + 4;
                v = make_float4(W[u * HID + k],        W[(20 + u) * HID + k],
                                W[(40 + u) * HID + k], W[(60 + u) * HID + k]);
            }
            sW[m][k][s][q] = v;
        }
        for (int idx = tid; idx < 2 * 4 * 5; idx += NTHR) {
            int i = idx / 20, s = (idx % 20) / 5, q = idx % 5;
            float4 v;
            if (q < 4) {
                int g = 20 * q + 5 * s;
                v = make_float4(Wih0[(g + 0) * 2 + i], Wih0[(g + 1) * 2 + i],
                                Wih0[(g + 2) * 2 + i], Wih0[(g + 3) * 2 + i]);
            } else {
                int u = 5 * s + 4;
                v = make_float4(Wih0[u * 2 + i],        Wih0[(20 + u) * 2 + i],
                                Wih0[(40 + u) * 2 + i], Wih0[(60 + u) * 2 + i]);
            }
            sWx[i][s][q] = v;
        }
        for (int idx = tid; idx < 2 * 4 * 5; idx += NTHR) {
            int l = idx / 20, s = (idx % 20) / 5, q = idx % 5;
            const float* bi = l ? bih1 : bih0;
            const float* bh = l ? bhh1 : bhh0;
            float4 v;
            if (q < 4) {
                int g = 20 * q + 5 * s;
                v = make_float4(bi[g] + bh[g],         bi[g + 1] + bh[g + 1],
                                bi[g + 2] + bh[g + 2], bi[g + 3] + bh[g + 3]);
            } else {
                int u = 5 * s + 4;
                v = make_float4(bi[u] + bh[u],           bi[20 + u] + bh[20 + u],
                                bi[40 + u] + bh[40 + u], bi[60 + u] + bh[60 + u]);
            }
            sBias[l][s][q] = v;
        }
    }

    // ---------------- init state ----------------
    float cA[2][5], cB[2][5], hA[2][5], hB[2][5];
#pragma unroll
    for (int j = 0; j < 5; j++) {
        int u = u0 + j;
        cA[0][j] = c0[(size_t)b0 * HID + u];
        cA[1][j] = c0[(size_t)b1 * HID + u];
        cB[0][j] = c0[(size_t)B * HID + (size_t)b0 * HID + u];
        cB[1][j] = c0[(size_t)B * HID + (size_t)b1 * HID + u];
        sHA[0][e0][u] = h0[(size_t)b0 * HID + u];
        sHA[0][e1][u] = h0[(size_t)b1 * HID + u];
        sHB[0][e0][u] = h0[(size_t)B * HID + (size_t)b0 * HID + u];
        sHB[0][e1][u] = h0[(size_t)B * HID + (size_t)b1 * HID + u];
    }
    __syncthreads();

    float lg[2][3] = {{0.f, 0.f, 0.f}, {0.f, 0.f, 0.f}};
    const float2* x2 = reinterpret_cast<const float2*>(x);

    // software-prefetched x for step t
    float2 xv0 = x2[b0];
    float2 xv1 = x2[b1];

#pragma unroll 1
    for (int t = 0; t < T_STEPS; t++) {
        const int cur = t & 1, nxt = cur ^ 1;

        // ---- prefetch this step's decoder weights (consumed at step end) ----
        float w0[5], w1[5], w2[5];
        {
            const float* wd = Wdec + t * HID + u0;
#pragma unroll
            for (int j = 0; j < 5; j++) {
                w0[j] = __ldg(wd + j);
                w1[j] = __ldg(wd + T_STEPS * HID + j);
                w2[j] = __ldg(wd + 2 * T_STEPS * HID + j);
            }
        }

        // ---- layer 1: bias + input proj + recurrent matvec ----
        ULL gpa[10], gpb[10];
        {
            const ulonglong2* bb = reinterpret_cast<const ulonglong2*>(&sBias[0][sub][0]);
#pragma unroll
            for (int q = 0; q < 5; q++) {
                gpa[2 * q] = bb[q].x;  gpa[2 * q + 1] = bb[q].y;
                gpb[2 * q] = bb[q].x;  gpb[2 * q + 1] = bb[q].y;
            }
        }
        mv_accum2(gpa, gpb, xv0.x, xv1.x, &sWx[0][sub][0]);
        mv_accum2(gpa, gpb, xv0.y, xv1.y, &sWx[1][sub][0]);
        {
            const float4* wbase = &sW[0][0][sub][0];
#pragma unroll 10
            for (int k = 0; k < HID; k++)
                mv_accum2(gpa, gpb, sHA[cur][e0][k], sHA[cur][e1][k],
                          wbase + (size_t)k * 20);
        }
        cell_update(gpa, cA[0], hA[0]);
        cell_update(gpb, cA[1], hA[1]);
#pragma unroll
        for (int j = 0; j < 5; j++) {
            sHA[nxt][e0][u0 + j] = hA[0][j];
            sHA[nxt][e1][u0 + j] = hA[1][j];
        }

        // ---- layer 2 RECURRENT matvec (independent of h1(t)) — before barrier ----
        ULL g2a[10], g2b[10];
        {
            const ulonglong2* bb = reinterpret_cast<const ulonglong2*>(&sBias[1][sub][0]);
#pragma unroll
            for (int q = 0; q < 5; q++) {
                g2a[2 * q] = bb[q].x;  g2a[2 * q + 1] = bb[q].y;
                g2b[2 * q] = bb[q].x;  g2b[2 * q + 1] = bb[q].y;
            }
        }
        {
            const float4* wbase = &sW[2][0][sub][0];
#pragma unroll 10
            for (int k = 0; k < HID; k++)
                mv_accum2(g2a, g2b, sHB[cur][e0][k], sHB[cur][e1][k],
                          wbase + (size_t)k * 20);
        }
        __syncthreads();   // h1(t) now visible from all warps

        // ---- layer 2 input matvec over h1(t) + cell update ----
        {
            const float4* wbase = &sW[1][0][sub][0];
#pragma unroll 10
            for (int k = 0; k < HID; k++)
                mv_accum2(g2a, g2b, sHA[nxt][e0][k], sHA[nxt][e1][k],
                          wbase + (size_t)k * 20);
        }
        cell_update(g2a, cB[0], hB[0]);
        cell_update(g2b, cB[1], hB[1]);
#pragma unroll
        for (int j = 0; j < 5; j++) {
            sHB[nxt][e0][u0 + j] = hB[0][j];
            sHB[nxt][e1][u0 + j] = hB[1][j];
        }

        // ---- fused decoder partials (weights preloaded at step top) ----
#pragma unroll
        for (int j = 0; j < 5; j++) {
            lg[0][0] = fmaf(hB[0][j], w0[j], lg[0][0]);
            lg[0][1] = fmaf(hB[0][j], w1[j], lg[0][1]);
            lg[0][2] = fmaf(hB[0][j], w2[j], lg[0][2]);
            lg[1][0] = fmaf(hB[1][j], w0[j], lg[1][0]);
            lg[1][1] = fmaf(hB[1][j], w1[j], lg[1][1]);
            lg[1][2] = fmaf(hB[1][j], w2[j], lg[1][2]);
        }

        // ---- prefetch x for next step (lands during barrier + next L1 phase) ----
        {
            int tn = (t + 1 < T_STEPS) ? (t + 1) : t;
            xv0 = x2[(size_t)tn * B + b0];
            xv1 = x2[(size_t)tn * B + b1];
        }
        __syncthreads();   // h2(t) visible; buffers safe to swap
    }

    // ---------------- outputs ----------------
    float* o_h = out + 2 * (size_t)B;
    float* o_c = o_h + 2 * (size_t)B * HID;
#pragma unroll
    for (int j = 0; j < 5; j++) {
        int u = u0 + j;
        o_h[(size_t)b0 * HID + u]                   = hA[0][j];
        o_h[(size_t)b1 * HID + u]                   = hA[1][j];
        o_h[(size_t)B * HID + (size_t)b0 * HID + u] = hB[0][j];
        o_h[(size_t)B * HID + (size_t)b1 * HID + u] = hB[1][j];
        o_c[(size_t)b0 * HID + u]                   = cA[0][j];
        o_c[(size_t)b1 * HID + u]                   = cA[1][j];
        o_c[(size_t)B * HID + (size_t)b0 * HID + u] = cB[0][j];
        o_c[(size_t)B * HID + (size_t)b1 * HID + u] = cB[1][j];
    }

    // reduce decoder partials across the 4 warps
#pragma unroll
    for (int a = 0; a < 3; a++) {
        sLG[a][sub][e0] = lg[0][a];
        sLG[a][sub][e1] = lg[1][a];
    }
    __syncthreads();

    if (sub == 0) {
#pragma unroll
        for (int ei = 0; ei < 2; ei++) {
            int e = (ei == 0) ? e0 : e1;
            int b = (ei == 0) ? b0 : b1;
            float logit0 = sLG[0][0][e] + sLG[0][1][e] + sLG[0][2][e] + sLG[0][3][e] + bdec[0];
            float logit1 = sLG[1][0][e] + sLG[1][1][e] + sLG[1][2][e] + sLG[1][3][e] + bdec[1];
            float logit2 = sLG[2][0][e] + sLG[2][1][e] + sLG[2][2][e] + sLG[2][3][e] + bdec[2];

            float m   = fmaxf(logit0, fmaxf(logit1, logit2));
            float lse = m + logf(expf(logit0 - m) + expf(logit1 - m) + expf(logit2 - m));

            const float tinyf = 1.17549435e-38f;
            float best = -1e30f, sel_logit = logit0;
            int act = 0;
#pragma unroll
            for (int a = 0; a < 3; a++) {
                unsigned bits = jax_random_bits_partitionable((unsigned)(b * 3 + a));
                float f  = __uint_as_float((bits >> 9) | 0x3f800000u) - 1.0f;
                float uu = fmaxf(tinyf, f + tinyf);
                float gmb = -logf(-logf(uu));
                float lgv = (a == 0) ? logit0 : (a == 1) ? logit1 : logit2;
                float v   = lgv + gmb;
                if (v > best) { best = v; act = a; sel_logit = lgv; }
            }
            out[b]     = (float)act;
            out[B + b] = sel_logit - lse;
        }
    }
}

extern "C" void kernel_launch(void* const* d_in, const int* in_sizes, int n_in,
                              void* d_out, int out_size) {
    const float* x    = (const float*)d_in[0];
    const float* h0   = (const float*)d_in[1];
    const float* c0   = (const float*)d_in[2];
    const float* Wih0 = (const float*)d_in[3];
    const float* Whh0 = (const float*)d_in[4];
    const float* bih0 = (const float*)d_in[5];
    const float* bhh0 = (const float*)d_in[6];
    const float* Wih1 = (const float*)d_in[7];
    const float* Whh1 = (const float*)d_in[8];
    const float* bih1 = (const float*)d_in[9];
    const float* bhh1 = (const float*)d_in[10];
    const float* Wdec = (const float*)d_in[11];
    const float* bdec = (const float*)d_in[12];

    int B = in_sizes[0] / (T_STEPS * 2);   // x is [T, B, 2]
    dim3 grid(B / EPB), block(NTHR);
    lstm_fused_kernel<<<grid, block>>>(x, h0, c0, Wih0, Whh0, bih0, bhh0,
                                       Wih1, Whh1, bih1, bhh1, Wdec, bdec,
                                       (float*)d_out, B);
}